// round 17
// baseline (speedup 1.0000x reference)
#include <cuda_runtime.h>
#include <math.h>

// Problem constants
#define B_   256
#define T_   200
#define H_   256
#define G3   768       // 3*H
#define VO   50001     // V+1

typedef unsigned long long ull;

// ---------------- device scratch (no allocs allowed) ----------------
__device__ __align__(16) float g_gx[(size_t)B_ * T_ * G3];  // 157 MB gates_x
__device__ __align__(16) float g_h[2][B_ * H_];             // double-buffered hidden state
__device__ unsigned g_cnt2[8 * 64];               // per-group barrier counters (256B stride)
__device__ unsigned g_gen2[8 * 64];               // per-group generations
__device__ int      g_is64;                       // input_ids dtype flag

// ---------------- packed f32x2 helpers ----------------
__device__ __forceinline__ ull ffma2(ull a, ull b, ull c) {
    ull d;
    asm("fma.rn.f32x2 %0, %1, %2, %3;" : "=l"(d) : "l"(a), "l"(b), "l"(c));
    return d;
}
__device__ __forceinline__ ull packf2(float lo, float hi) {
    ull u;
    asm("mov.b64 %0, {%1, %2};" : "=l"(u) : "f"(lo), "f"(hi));
    return u;
}
__device__ __forceinline__ void unpackf2(ull u, float& lo, float& hi) {
    asm("mov.b64 {%0, %1}, %2;" : "=f"(lo), "=f"(hi) : "l"(u));
}
__device__ __forceinline__ float sumf2(ull u) {
    float lo, hi; unpackf2(u, lo, hi);
    return lo + hi;
}
__device__ __forceinline__ float sigmoidf_(float x) {
    return 1.0f / (1.0f + expf(-x));
}

// ---------------- per-group software barrier (16 CTAs, all resident) --------
__device__ __forceinline__ void group_sync_(int gid) {
    __syncthreads();
    if (threadIdx.x == 0) {
        unsigned* cntp = &g_cnt2[gid * 64];
        volatile unsigned* genp = &g_gen2[gid * 64];
        unsigned gen = *genp;
        __threadfence();
        if (atomicAdd(cntp, 1u) == 15u) {
            *cntp = 0u;
            __threadfence();
            atomicAdd((unsigned*)&g_gen2[gid * 64], 1u);
        } else {
            while (*genp == gen) { }
            __threadfence();
        }
    }
    __syncthreads();
}

// ---------------- dtype detect: int64 vs int32 input_ids ----------------
__global__ void detect_kernel(const unsigned* idw) {
    __shared__ int any;
    if (threadIdx.x == 0) any = 0;
    __syncthreads();
    int local = 0;
    for (int i = threadIdx.x; i < 2048; i += blockDim.x)
        if (idw[2 * i + 1] != 0u) local = 1;
    if (local) atomicOr(&any, 1);
    __syncthreads();
    if (threadIdx.x == 0) g_is64 = (any == 0) ? 1 : 0;
}

// ============================================================================
// 8x8-per-thread GEMM core (32 rows x 256 cols per CTA, 128 threads).
// A staged PRE-DUPLICATED as f32x2 pairs in xs2[k][m]; B staged [k][n] with
// 260-float rows (65 16B-units, odd -> conflict-free LDS.128 streams).
// Lane layout: tx = tid&31 -> cols {tx*4..+3} and {128+tx*4..+3};
//              ty = tid>>5 -> rows ty*8..ty*8+7.  Warp = fixed ty (broadcast A).
// ============================================================================

#define GEMM_CORE(xs2, ws, acc, ty, tx)                                        \
    _Pragma("unroll 8")                                                        \
    for (int k = 0; k < 32; ++k) {                                             \
        const ull* ap_ = &xs2[k][(ty) * 8];                                    \
        ulonglong2 a01_ = *reinterpret_cast<const ulonglong2*>(ap_);           \
        ulonglong2 a23_ = *reinterpret_cast<const ulonglong2*>(ap_ + 2);       \
        ulonglong2 a45_ = *reinterpret_cast<const ulonglong2*>(ap_ + 4);       \
        ulonglong2 a67_ = *reinterpret_cast<const ulonglong2*>(ap_ + 6);       \
        ulonglong2 b0_ = *reinterpret_cast<const ulonglong2*>(&ws[k][(tx)*4]); \
        ulonglong2 b1_ = *reinterpret_cast<const ulonglong2*>(&ws[k][128 + (tx)*4]); \
        ull am_[8] = {a01_.x, a01_.y, a23_.x, a23_.y, a45_.x, a45_.y, a67_.x, a67_.y}; \
        _Pragma("unroll")                                                      \
        for (int m = 0; m < 8; ++m) {                                          \
            acc[m][0] = ffma2(am_[m], b0_.x, acc[m][0]);                       \
            acc[m][1] = ffma2(am_[m], b0_.y, acc[m][1]);                       \
            acc[m][2] = ffma2(am_[m], b1_.x, acc[m][2]);                       \
            acc[m][3] = ffma2(am_[m], b1_.y, acc[m][3]);                       \
        }                                                                      \
    }

// ---------------- phase 1: gates_x = emb[ids] @ w_ih + b_ih ----------------
// CTA = 32 t-rows (one batch element) x 256 gate-cols. grid (3, 7, 256).
// Software-pipelined: next k-chunk's LDGs issued into registers before the dot.
__global__ void __launch_bounds__(128) gates_kernel(const void* __restrict__ ids_raw,
                                                    const int* __restrict__ lengths,
                                                    const float* __restrict__ emb,
                                                    const float* __restrict__ w_ih,
                                                    const float* __restrict__ b_ih) {
    __shared__ __align__(16) ull   xs2[32][36];   // [k][m] dup pairs
    __shared__ __align__(16) float ws[32][260];   // [k][n]
    __shared__ int ids_s[32];

    const int b   = blockIdx.z;
    const int len = lengths[b];
    const int t0  = blockIdx.y * 32;
    if (t0 >= len) return;
    const int gc0 = blockIdx.x * 256;
    const int tid = threadIdx.x;
    const int is64 = g_is64;

    if (tid < 32) {
        int t = t0 + tid;
        long long id = 0;
        if (t < T_) {
            long long ofs = (long long)b * T_ + t;
            id = is64 ? ((const long long*)ids_raw)[ofs]
                      : (long long)((const int*)ids_raw)[ofs];
        }
        ids_s[tid] = (int)id;
    }

    const int tx = tid & 31, ty = tid >> 5;

    ull acc[8][4];
    {
        float4 bl = __ldg(reinterpret_cast<const float4*>(b_ih + gc0 + tx * 4));
        float4 bh = __ldg(reinterpret_cast<const float4*>(b_ih + gc0 + 128 + tx * 4));
        ull i0 = packf2(bl.x, bl.y), i1 = packf2(bl.z, bl.w);
        ull i2 = packf2(bh.x, bh.y), i3 = packf2(bh.z, bh.w);
#pragma unroll
        for (int m = 0; m < 8; ++m) {
            acc[m][0] = i0; acc[m][1] = i1; acc[m][2] = i2; acc[m][3] = i3;
        }
    }
    __syncthreads();   // ids_s ready

    // precomputed staging indices
    const int pa_kq0 = tid >> 5,        pa_r0 = tid & 31;          // it 0
    const int pa_kq1 = (128 + tid) >> 5, pa_r1 = (128 + tid) & 31; // it 1

    float4 px[2];
    float4 pw[16];

    // initial load (kc = 0)
    px[0] = __ldg(reinterpret_cast<const float4*>(emb + (long long)ids_s[pa_r0] * H_ + pa_kq0 * 4));
    px[1] = __ldg(reinterpret_cast<const float4*>(emb + (long long)ids_s[pa_r1] * H_ + pa_kq1 * 4));
#pragma unroll
    for (int it = 0; it < 16; ++it) {
        int flat = it * 128 + tid;
        int k = flat >> 6, nq = flat & 63;
        pw[it] = __ldg(reinterpret_cast<const float4*>(
            w_ih + (long long)k * G3 + gc0 + nq * 4));
    }
    // store kc = 0
    {
        xs2[pa_kq0 * 4 + 0][pa_r0] = packf2(px[0].x, px[0].x);
        xs2[pa_kq0 * 4 + 1][pa_r0] = packf2(px[0].y, px[0].y);
        xs2[pa_kq0 * 4 + 2][pa_r0] = packf2(px[0].z, px[0].z);
        xs2[pa_kq0 * 4 + 3][pa_r0] = packf2(px[0].w, px[0].w);
        xs2[pa_kq1 * 4 + 0][pa_r1] = packf2(px[1].x, px[1].x);
        xs2[pa_kq1 * 4 + 1][pa_r1] = packf2(px[1].y, px[1].y);
        xs2[pa_kq1 * 4 + 2][pa_r1] = packf2(px[1].z, px[1].z);
        xs2[pa_kq1 * 4 + 3][pa_r1] = packf2(px[1].w, px[1].w);
#pragma unroll
        for (int it = 0; it < 16; ++it) {
            int flat = it * 128 + tid;
            int k = flat >> 6, nq = flat & 63;
            *reinterpret_cast<float4*>(&ws[k][nq * 4]) = pw[it];
        }
    }
    __syncthreads();

    for (int kc = 0; kc < 8; ++kc) {
        // prefetch next chunk into registers (latency hides under the dot)
        if (kc < 7) {
            const int k0 = (kc + 1) * 32;
            px[0] = __ldg(reinterpret_cast<const float4*>(
                emb + (long long)ids_s[pa_r0] * H_ + k0 + pa_kq0 * 4));
            px[1] = __ldg(reinterpret_cast<const float4*>(
                emb + (long long)ids_s[pa_r1] * H_ + k0 + pa_kq1 * 4));
#pragma unroll
            for (int it = 0; it < 16; ++it) {
                int flat = it * 128 + tid;
                int k = flat >> 6, nq = flat & 63;
                pw[it] = __ldg(reinterpret_cast<const float4*>(
                    w_ih + (long long)(k0 + k) * G3 + gc0 + nq * 4));
            }
        }

        GEMM_CORE(xs2, ws, acc, ty, tx)

        if (kc < 7) {
            __syncthreads();
            xs2[pa_kq0 * 4 + 0][pa_r0] = packf2(px[0].x, px[0].x);
            xs2[pa_kq0 * 4 + 1][pa_r0] = packf2(px[0].y, px[0].y);
            xs2[pa_kq0 * 4 + 2][pa_r0] = packf2(px[0].z, px[0].z);
            xs2[pa_kq0 * 4 + 3][pa_r0] = packf2(px[0].w, px[0].w);
            xs2[pa_kq1 * 4 + 0][pa_r1] = packf2(px[1].x, px[1].x);
            xs2[pa_kq1 * 4 + 1][pa_r1] = packf2(px[1].y, px[1].y);
            xs2[pa_kq1 * 4 + 2][pa_r1] = packf2(px[1].z, px[1].z);
            xs2[pa_kq1 * 4 + 3][pa_r1] = packf2(px[1].w, px[1].w);
#pragma unroll
            for (int it = 0; it < 16; ++it) {
                int flat = it * 128 + tid;
                int k = flat >> 6, nq = flat & 63;
                *reinterpret_cast<float4*>(&ws[k][nq * 4]) = pw[it];
            }
            __syncthreads();
        }
    }

#pragma unroll
    for (int m = 0; m < 8; ++m) {
        int t = t0 + ty * 8 + m;
        if (t < len) {
            float* o = g_gx + ((long long)b * T_ + t) * G3 + gc0;
            ulonglong2 lo, hi;
            lo.x = acc[m][0]; lo.y = acc[m][1];
            hi.x = acc[m][2]; hi.y = acc[m][3];
            *reinterpret_cast<ulonglong2*>(o + tx * 4)       = lo;
            *reinterpret_cast<ulonglong2*>(o + 128 + tx * 4) = hi;
        }
    }
}

// ---------------- phase 2: persistent GRU recurrence ----------------
// grid = (16 unit tiles x 8 batch groups) = 128 CTAs, 256 threads.
// Warp remap: warp wp -> rows {16*(wp&1)..+15}, col-block (wp>>1)*12;
// lane: r = (lane&15)+16*(wp&1), colgroup cg = lane>>4 -> cols cb*12+cg*6..+5.
// h LDS: 16 distinct rows -> 2 wf per LDS.128; w LDS: 2 addrs/instr -> 1 wf.
__global__ void __launch_bounds__(256, 1) rec_kernel(const int* __restrict__ lengths,
                                                     const float* __restrict__ w_hh,
                                                     const float* __restrict__ b_hh) {
    extern __shared__ float sm[];
    float (*w_s)[260]  = (float(*)[260])sm;                           // 48 x 260
    float (*h_s)[260]  = (float(*)[260])(sm + 48 * 260);              // 32 x 260
    float (*rec_s)[49] = (float(*)[49]) (sm + 80 * 260);              // 32 x 49
    float (*gx_b0)[52] = (float(*)[52]) (sm + 80 * 260 + 32 * 49);    // 32 x 52
    float (*gx_b1)[52] = (float(*)[52]) (sm + 80 * 260 + 32 * 49 + 32 * 52);
    __shared__ int len_s[32];

    const int u0  = blockIdx.x * 16;
    const int b0  = blockIdx.y * 32;
    const int gid = blockIdx.y;
    const int tid = threadIdx.x;
    const int lane = tid & 31, wp = tid >> 5;   // 8 warps
    const int r   = (lane & 15) + 16 * (wp & 1);   // row handled by this lane
    const int cl0 = (wp >> 1) * 12 + (lane >> 4) * 6;  // first of 6 cols

    // persistent weight slice: w_s[c][k] = w_hh[k*768 + gate*256 + u0 + u]
    for (int i = tid; i < 48 * H_; i += 256) {
        int c = i % 48, k = i / 48;
        w_s[c][k] = __ldg(w_hh + (long long)k * G3 + (c >> 4) * H_ + u0 + (c & 15));
    }
    if (tid < 32) len_s[tid] = lengths[b0 + tid];

    float bias[6];
#pragma unroll
    for (int c = 0; c < 6; ++c) {
        int cl = cl0 + c;
        bias[c] = b_hh[(cl >> 4) * H_ + u0 + (cl & 15)];
    }

    // zero owned region of h buffer 0
    for (int i = tid; i < 512; i += 256) {
        int rr2 = i >> 4, u = i & 15;
        g_h[0][(b0 + rr2) * H_ + u0 + u] = 0.f;
    }
    // stage gx for t=0 into buffer 0 (vectorized, 16B-aligned rows)
#pragma unroll
    for (int it = 0; it < 2; ++it) {
        int i = it * 256 + tid;
        int rr2 = i >> 4, s = i & 15;
        if (s < 12) {
            int gate = s >> 2, q = s & 3;
            float4 v = __ldg(reinterpret_cast<const float4*>(
                g_gx + ((long long)(b0 + rr2) * T_) * G3 + gate * H_ + u0 + q * 4));
            *reinterpret_cast<float4*>(&gx_b0[rr2][gate * 16 + q * 4]) = v;
        }
    }
    group_sync_(gid);

    for (int t = 0; t < T_; ++t) {
        const int cur = t & 1;
        const float* hc = g_h[cur];
        float* hn = g_h[cur ^ 1];
        float (*gxc)[52] = cur ? gx_b1 : gx_b0;
        float (*gxn)[52] = cur ? gx_b0 : gx_b1;

        // load h tile: batch all 8 LDG.128.cg first (MLP=8), then STS
        float4 hb[8];
#pragma unroll
        for (int j = 0; j < 8; ++j) {
            int i = tid + j * 256;
            int rr2 = i >> 6, q = i & 63;
            hb[j] = __ldcg(reinterpret_cast<const float4*>(hc + (b0 + rr2) * H_ + q * 4));
        }
#pragma unroll
        for (int j = 0; j < 8; ++j) {
            int i = tid + j * 256;
            int rr2 = i >> 6, q = i & 63;
            *reinterpret_cast<float4*>(&h_s[rr2][q * 4]) = hb[j];
        }
        __syncthreads();

        ull acc[6];
#pragma unroll
        for (int c = 0; c < 6; ++c) {
            int cl = cl0 + c;
            float add = bias[c] + (cl < 32 ? gxc[r][cl] : 0.f);
            acc[c] = packf2(add, 0.f);
        }
        const float* hrow = &h_s[r][0];
        const float* w0   = &w_s[cl0][0];
#pragma unroll 4
        for (int k = 0; k < H_; k += 8) {
            ulonglong2 h01 = *reinterpret_cast<const ulonglong2*>(hrow + k);
            ulonglong2 h23 = *reinterpret_cast<const ulonglong2*>(hrow + k + 4);
#pragma unroll
            for (int c = 0; c < 6; ++c) {
                const float* wr = w0 + c * 260 + k;
                ulonglong2 w01 = *reinterpret_cast<const ulonglong2*>(wr);
                ulonglong2 w23 = *reinterpret_cast<const ulonglong2*>(wr + 4);
                acc[c] = ffma2(h01.x, w01.x, acc[c]);
                acc[c] = ffma2(h01.y, w01.y, acc[c]);
                acc[c] = ffma2(h23.x, w23.x, acc[c]);
                acc[c] = ffma2(h23.y, w23.y, acc[c]);
            }
        }
#pragma unroll
        for (int c = 0; c < 6; ++c) rec_s[r][cl0 + c] = sumf2(acc[c]);
        __syncthreads();

        // gate combine + masked h update
        for (int i = tid; i < 512; i += 256) {
            int rr2 = i >> 4, u = i & 15;
            float z  = sigmoidf_(rec_s[rr2][u]);          // xz + rz (+bias)
            float rb = sigmoidf_(rec_s[rr2][16 + u]);     // xr + rr (+bias)
            float hh = tanhf(gxc[rr2][32 + u] + rb * rec_s[rr2][32 + u]);
            float ho = h_s[rr2][u0 + u];
            float hv2 = z * ho + (1.0f - z) * hh;
            hn[(b0 + rr2) * H_ + u0 + u] = (t < len_s[rr2]) ? hv2 : ho;
        }
        // prefetch next step's gx BEFORE the barrier (latency hides in wait)
        if (t + 1 < T_) {
#pragma unroll
            for (int it = 0; it < 2; ++it) {
                int i = it * 256 + tid;
                int rr2 = i >> 4, s = i & 15;
                if (s < 12) {
                    int gate = s >> 2, q = s & 3;
                    float4 v = __ldg(reinterpret_cast<const float4*>(
                        g_gx + ((long long)(b0 + rr2) * T_ + (t + 1)) * G3 +
                        gate * H_ + u0 + q * 4));
                    *reinterpret_cast<float4*>(&gxn[rr2][gate * 16 + q * 4]) = v;
                }
            }
        }
        group_sync_(gid);
    }
    // T_=200 even -> final state in g_h[0]
}

// ---------------- phase 3: logits = h_final @ emb.T ----------------
// CTA = 32 batch rows x 256 vocab cols, 128 threads. grid (8, 196).
// Software-pipelined: next k-chunk's LDGs issued into registers before the dot.
__global__ void __launch_bounds__(128) logits_kernel(const float* __restrict__ emb,
                                                     float* __restrict__ out) {
    __shared__ __align__(16) ull   hs2[32][36];   // [k][m] dup pairs
    __shared__ __align__(16) float es[32][260];   // [k][n]

    const int b0 = blockIdx.x * 32;
    const int v0 = blockIdx.y * 256;
    const int tid = threadIdx.x;
    const int tx = tid & 31, ty = tid >> 5;
    const float* hf = g_h[0];

    ull acc[8][4];
#pragma unroll
    for (int m = 0; m < 8; ++m)
#pragma unroll
        for (int q = 0; q < 4; ++q) acc[m][q] = 0ull;

    const int pa_kq0 = tid >> 5,         pa_r0 = tid & 31;
    const int pa_kq1 = (128 + tid) >> 5, pa_r1 = (128 + tid) & 31;

    float4 ph[2];
    float4 pe[16];

    // initial load (kc = 0)
    ph[0] = *reinterpret_cast<const float4*>(hf + (long long)(b0 + pa_r0) * H_ + pa_kq0 * 4);
    ph[1] = *reinterpret_cast<const float4*>(hf + (long long)(b0 + pa_r1) * H_ + pa_kq1 * 4);
#pragma unroll
    for (int it = 0; it < 16; ++it) {
        int flat = it * 128 + tid;
        int kq = flat >> 8, n = flat & 255;
        int vg = min(v0 + n, VO - 1);
        pe[it] = __ldg(reinterpret_cast<const float4*>(emb + (long long)vg * H_ + kq * 4));
    }
    // store kc = 0
    {
        hs2[pa_kq0 * 4 + 0][pa_r0] = packf2(ph[0].x, ph[0].x);
        hs2[pa_kq0 * 4 + 1][pa_r0] = packf2(ph[0].y, ph[0].y);
        hs2[pa_kq0 * 4 + 2][pa_r0] = packf2(ph[0].z, ph[0].z);
        hs2[pa_kq0 * 4 + 3][pa_r0] = packf2(ph[0].w, ph[0].w);
        hs2[pa_kq1 * 4 + 0][pa_r1] = packf2(ph[1].x, ph[1].x);
        hs2[pa_kq1 * 4 + 1][pa_r1] = packf2(ph[1].y, ph[1].y);
        hs2[pa_kq1 * 4 + 2][pa_r1] = packf2(ph[1].z, ph[1].z);
        hs2[pa_kq1 * 4 + 3][pa_r1] = packf2(ph[1].w, ph[1].w);
#pragma unroll
        for (int it = 0; it < 16; ++it) {
            int flat = it * 128 + tid;
            int kq = flat >> 8, n = flat & 255;
            es[kq * 4 + 0][n] = pe[it].x;
            es[kq * 4 + 1][n] = pe[it].y;
            es[kq * 4 + 2][n] = pe[it].z;
            es[kq * 4 + 3][n] = pe[it].w;
        }
    }
    __syncthreads();

    for (int kc = 0; kc < 8; ++kc) {
        if (kc < 7) {
            const int k0 = (kc + 1) * 32;
            ph[0] = *reinterpret_cast<const float4*>(
                hf + (long long)(b0 + pa_r0) * H_ + k0 + pa_kq0 * 4);
            ph[1] = *reinterpret_cast<const float4*>(
                hf + (long long)(b0 + pa_r1) * H_ + k0 + pa_kq1 * 4);
#pragma unroll
            for (int it = 0; it < 16; ++it) {
                int flat = it * 128 + tid;
                int kq = flat >> 8, n = flat & 255;
                int vg = min(v0 + n, VO - 1);
                pe[it] = __ldg(reinterpret_cast<const float4*>(
                    emb + (long long)vg * H_ + k0 + kq * 4));
            }
        }

        GEMM_CORE(hs2, es, acc, ty, tx)

        if (kc < 7) {
            __syncthreads();
            hs2[pa_kq0 * 4 + 0][pa_r0] = packf2(ph[0].x, ph[0].x);
            hs2[pa_kq0 * 4 + 1][pa_r0] = packf2(ph[0].y, ph[0].y);
            hs2[pa_kq0 * 4 + 2][pa_r0] = packf2(ph[0].z, ph[0].z);
            hs2[pa_kq0 * 4 + 3][pa_r0] = packf2(ph[0].w, ph[0].w);
            hs2[pa_kq1 * 4 + 0][pa_r1] = packf2(ph[1].x, ph[1].x);
            hs2[pa_kq1 * 4 + 1][pa_r1] = packf2(ph[1].y, ph[1].y);
            hs2[pa_kq1 * 4 + 2][pa_r1] = packf2(ph[1].z, ph[1].z);
            hs2[pa_kq1 * 4 + 3][pa_r1] = packf2(ph[1].w, ph[1].w);
#pragma unroll
            for (int it = 0; it < 16; ++it) {
                int flat = it * 128 + tid;
                int kq = flat >> 8, n = flat & 255;
                es[kq * 4 + 0][n] = pe[it].x;
                es[kq * 4 + 1][n] = pe[it].y;
                es[kq * 4 + 2][n] = pe[it].z;
                es[kq * 4 + 3][n] = pe[it].w;
            }
            __syncthreads();
        }
    }

    // scalar stores (VO odd -> rows only 4B-aligned)
#pragma unroll
    for (int m = 0; m < 8; ++m) {
        float* orow = out + (long long)(b0 + ty * 8 + m) * VO;
#pragma unroll
        for (int q = 0; q < 4; ++q) {
            float lo, hi; unpackf2(acc[m][q], lo, hi);
            int v = v0 + ((q < 2) ? (tx * 4 + 2 * q) : (128 + tx * 4 + 2 * (q - 2)));
            if (v < VO)     orow[v]     = lo;
            if (v + 1 < VO) orow[v + 1] = hi;
        }
    }
}

// ---------------- launch ----------------
extern "C" void kernel_launch(void* const* d_in, const int* in_sizes, int n_in,
                              void* d_out, int out_size) {
    const void*  ids     = d_in[0];                  // int64 or int32 [B,T]
    const int*   lengths = (const int*)d_in[1];      // int32 [B]
    const float* emb     = (const float*)d_in[2];    // [V+1, H]
    const float* w_ih    = (const float*)d_in[3];    // [H, 3H]
    const float* w_hh    = (const float*)d_in[4];    // [H, 3H]
    const float* b_ih    = (const float*)d_in[5];    // [3H]
    const float* b_hh    = (const float*)d_in[6];    // [3H]
    float* out = (float*)d_out;

    const int SMEM_REC = (80 * 260 + 32 * 49 + 2 * 32 * 52) * 4;   // 102,784 B

    cudaFuncSetAttribute(rec_kernel, cudaFuncAttributeMaxDynamicSharedMemorySize, SMEM_REC);

    detect_kernel<<<1, 256>>>((const unsigned*)ids);

    gates_kernel<<<dim3(3, 7, B_), 128>>>(ids, lengths, emb, w_ih, b_ih);

    rec_kernel<<<dim3(16, 8), 256, SMEM_REC>>>(lengths, w_hh, b_hh);

    logits_kernel<<<dim3(8, 196), 128>>>(emb, out);
}